// round 1
// baseline (speedup 1.0000x reference)
#include <cuda_runtime.h>
#include <math.h>

#define B_ 2
#define W_ 2048
#define C_ 1024
#define N_ 16
#define K_ 64
#define HEADS (B_*N_)

// Scratch (static device globals: allocation-free per harness rules)
__device__ float g_P [B_*N_*W_*K_];   // P in [b][n][w][k] layout (16.8 MB)
__device__ float g_M [HEADS*K_*K_];   // mm = (tril(P^T g))(tril(P^T g))^T per head
__device__ float g_Ng[B_*W_*C_];      // nudged in [b][w][c] layout (16.8 MB)

// ---------------------------------------------------------------------------
// GEMM: out[r][c] = sum_k A[r][k] * Wt[c][k] + bias[c]
// MODE 0 (proj): A = param, write to g_P in head layout
// MODE 1 (mix):  A = g_Ng,  write to out param in [r][c] layout
// 64x64 tile, 16x16 threads, 4x4 micro, k-tile 16.
// ---------------------------------------------------------------------------
template<int MODE>
__global__ __launch_bounds__(256)
void gemm_kernel(const float* __restrict__ A, const float* __restrict__ Wt,
                 const float* __restrict__ bias, float* __restrict__ out) {
    __shared__ __align__(16) float As[64*17];
    __shared__ __align__(16) float Bs[64*17];
    const int tx = threadIdx.x, ty = threadIdx.y;
    const int t  = ty*16 + tx;
    const int r0 = blockIdx.y*64, c0 = blockIdx.x*64;

    const float* Ain = (MODE == 0) ? A : g_Ng;

    float acc[4][4] = {};
    const int lr = t >> 2;            // 0..63
    const int lk = (t & 3) * 4;       // 0,4,8,12
    const float* Arow = Ain + (size_t)(r0 + lr)*C_ + lk;
    const float* Brow = Wt  + (size_t)(c0 + lr)*C_ + lk;

    for (int k0 = 0; k0 < C_; k0 += 16) {
        float4 va = *(const float4*)(Arow + k0);
        float4 vb = *(const float4*)(Brow + k0);
        As[lr*17+lk+0]=va.x; As[lr*17+lk+1]=va.y; As[lr*17+lk+2]=va.z; As[lr*17+lk+3]=va.w;
        Bs[lr*17+lk+0]=vb.x; Bs[lr*17+lk+1]=vb.y; Bs[lr*17+lk+2]=vb.z; Bs[lr*17+lk+3]=vb.w;
        __syncthreads();
        #pragma unroll
        for (int kk = 0; kk < 16; kk++) {
            float a[4], b[4];
            #pragma unroll
            for (int i = 0; i < 4; i++) a[i] = As[(ty*4+i)*17 + kk];
            #pragma unroll
            for (int j = 0; j < 4; j++) b[j] = Bs[(tx*4+j)*17 + kk];
            #pragma unroll
            for (int i = 0; i < 4; i++)
                #pragma unroll
                for (int j = 0; j < 4; j++)
                    acc[i][j] = fmaf(a[i], b[j], acc[i][j]);
        }
        __syncthreads();
    }

    #pragma unroll
    for (int i = 0; i < 4; i++) {
        const int r = r0 + ty*4 + i;
        #pragma unroll
        for (int j = 0; j < 4; j++) {
            const int c = c0 + tx*4 + j;
            const float v = acc[i][j] + bias[c];
            if (MODE == 0) {
                const int b = r >> 11, w = r & (W_-1);
                const int n = c >> 6,  k = c & (K_-1);
                g_P[(((size_t)(b*N_+n))*W_ + w)*K_ + k] = v;
            } else {
                out[(size_t)r*C_ + c] = v;
            }
        }
    }
}

// ---------------------------------------------------------------------------
// Per-head M build: m[k][l] = sum_w P[w][k]*G[w][l]; mask l<=k; mm = m m^T
// ---------------------------------------------------------------------------
__global__ __launch_bounds__(256)
void mbuild_kernel(const float* __restrict__ G) {
    __shared__ __align__(16) float sb[64*65];   // phase1: Ps[32*64] + Gs[32*64]
    float* Ps = sb;
    float* Gs = sb + 2048;
    const int tx = threadIdx.x, ty = threadIdx.y;
    const int t  = ty*16 + tx;
    const int bn = blockIdx.x;
    const int n  = bn & (N_-1);
    const float* Pp = g_P + (size_t)bn*W_*K_;
    const float* Gp = G   + (size_t)n *W_*K_;

    float m[4][4] = {};
    for (int w0 = 0; w0 < W_; w0 += 32) {
        #pragma unroll
        for (int s = 0; s < 2; s++) {
            const int i4 = t + s*256;
            ((float4*)Ps)[i4] = ((const float4*)(Pp + (size_t)w0*K_))[i4];
            ((float4*)Gs)[i4] = ((const float4*)(Gp + (size_t)w0*K_))[i4];
        }
        __syncthreads();
        #pragma unroll 8
        for (int ww = 0; ww < 32; ww++) {
            float a[4];
            #pragma unroll
            for (int i = 0; i < 4; i++) a[i] = Ps[ww*64 + ty*4 + i];
            const float4 b4 = *(const float4*)&Gs[ww*64 + tx*4];
            const float b[4] = {b4.x, b4.y, b4.z, b4.w};
            #pragma unroll
            for (int i = 0; i < 4; i++)
                #pragma unroll
                for (int j = 0; j < 4; j++)
                    m[i][j] = fmaf(a[i], b[j], m[i][j]);
        }
        __syncthreads();
    }
    // lower-triangular mask: keep if col <= row
    #pragma unroll
    for (int i = 0; i < 4; i++)
        #pragma unroll
        for (int j = 0; j < 4; j++)
            if (tx*4 + j > ty*4 + i) m[i][j] = 0.f;
    // masked m -> shared (pitch 65)
    #pragma unroll
    for (int i = 0; i < 4; i++)
        #pragma unroll
        for (int j = 0; j < 4; j++)
            sb[(ty*4+i)*65 + tx*4 + j] = m[i][j];
    __syncthreads();
    float mm[4][4] = {};
    #pragma unroll 8
    for (int jj = 0; jj < 64; jj++) {
        float a[4], b[4];
        #pragma unroll
        for (int i = 0; i < 4; i++) a[i] = sb[(ty*4+i)*65 + jj];
        #pragma unroll
        for (int j = 0; j < 4; j++) b[j] = sb[(tx*4+j)*65 + jj];
        #pragma unroll
        for (int i = 0; i < 4; i++)
            #pragma unroll
            for (int j = 0; j < 4; j++)
                mm[i][j] = fmaf(a[i], b[j], mm[i][j]);
    }
    #pragma unroll
    for (int i = 0; i < 4; i++)
        #pragma unroll
        for (int j = 0; j < 4; j++)
            g_M[(size_t)bn*K_*K_ + (ty*4+i)*K_ + tx*4 + j] = mm[i][j];
}

// ---------------------------------------------------------------------------
// Flash attention per (head, 64-query tile). Q' = Pq @ M, S = Q' Kt / 8,
// causal online softmax, O += Ptilde @ V (V == K block of P). Writes nudged
// in [b][w][c] layout.
// Dynamic smem: Qm_s[64*64] + Ps_s[64*64] + Kt_s[64*65] = 49408 B.
// ---------------------------------------------------------------------------
__global__ __launch_bounds__(256)
void flash_kernel() {
    extern __shared__ __align__(16) float sm[];
    float* Qm_s = sm;          // [64][64]  Q' (pitch 64, row-broadcast reads)
    float* Ps_s = sm + 4096;   // [64][64]  exp-scores / prologue Pq
    float* Kt_s = sm + 8192;   // [64][65]  K tile transposed [dim][key] / prologue M

    const int tx = threadIdx.x, ty = threadIdx.y;
    const int t  = ty*16 + tx;
    const int bn = blockIdx.y;
    const int b  = bn >> 4, n = bn & 15;
    const int qt = (int)(gridDim.x - 1) - (int)blockIdx.x;  // heavy tiles first
    const int w0 = qt * 64;
    const float* Pp = g_P + (size_t)bn*W_*K_;
    const float* Mp = g_M + (size_t)bn*K_*K_;

    // Prologue: Pq -> Ps_s, M -> Kt_s (flat), compute Qm
    #pragma unroll
    for (int s = 0; s < 4; s++) {
        const int i4 = t + s*256;
        ((float4*)Ps_s)[i4] = ((const float4*)(Pp + (size_t)w0*K_))[i4];
        ((float4*)Kt_s)[i4] = ((const float4*)Mp)[i4];
    }
    __syncthreads();
    {
        float q[4][4] = {};
        #pragma unroll 8
        for (int kk = 0; kk < 64; kk++) {
            float a[4], bb[4];
            #pragma unroll
            for (int i = 0; i < 4; i++) a[i]  = Ps_s[(ty*4+i)*64 + kk];
            #pragma unroll
            for (int j = 0; j < 4; j++) bb[j] = Kt_s[kk*64 + tx*4 + j];
            #pragma unroll
            for (int i = 0; i < 4; i++)
                #pragma unroll
                for (int j = 0; j < 4; j++)
                    q[i][j] = fmaf(a[i], bb[j], q[i][j]);
        }
        #pragma unroll
        for (int i = 0; i < 4; i++)
            #pragma unroll
            for (int j = 0; j < 4; j++)
                Qm_s[(ty*4+i)*64 + tx*4 + j] = q[i][j];
    }

    float mrun[4], lrun[4], O[4][4] = {};
    #pragma unroll
    for (int i = 0; i < 4; i++) { mrun[i] = -INFINITY; lrun[i] = 0.f; }

    for (int v0 = 0; v0 <= w0; v0 += 64) {
        __syncthreads();  // Qm visible (first iter); Kt_s/Ps_s free (later iters)
        // Load K tile transposed: Kt_s[dim][key], pitch 65
        {
            const int row = t >> 2;          // key index 0..63
            const int d0  = (t & 3) * 16;    // dim base
            const float* src = Pp + (size_t)(v0 + row)*K_ + d0;
            #pragma unroll
            for (int qq = 0; qq < 4; qq++) {
                const float4 v = *(const float4*)(src + qq*4);
                Kt_s[(d0+qq*4+0)*65 + row] = v.x;
                Kt_s[(d0+qq*4+1)*65 + row] = v.y;
                Kt_s[(d0+qq*4+2)*65 + row] = v.z;
                Kt_s[(d0+qq*4+3)*65 + row] = v.w;
            }
        }
        __syncthreads();
        // GEMM1: S = Qm @ K^T
        float s[4][4] = {};
        #pragma unroll 8
        for (int kk = 0; kk < 64; kk++) {
            float a[4], bb[4];
            #pragma unroll
            for (int i = 0; i < 4; i++) a[i]  = Qm_s[(ty*4+i)*64 + kk];
            #pragma unroll
            for (int j = 0; j < 4; j++) bb[j] = Kt_s[kk*65 + tx*4 + j];
            #pragma unroll
            for (int i = 0; i < 4; i++)
                #pragma unroll
                for (int j = 0; j < 4; j++)
                    s[i][j] = fmaf(a[i], bb[j], s[i][j]);
        }
        const bool diag = (v0 == w0);
        #pragma unroll
        for (int i = 0; i < 4; i++)
            #pragma unroll
            for (int j = 0; j < 4; j++) {
                s[i][j] *= 0.125f;                       // 1/sqrt(64)
                if (diag && (tx*4 + j > ty*4 + i)) s[i][j] = -INFINITY;
            }
        // Online softmax (row groups of 16 tx-lanes; half-warp shuffles)
        #pragma unroll
        for (int i = 0; i < 4; i++) {
            float rmax = fmaxf(fmaxf(s[i][0], s[i][1]), fmaxf(s[i][2], s[i][3]));
            #pragma unroll
            for (int off = 8; off >= 1; off >>= 1)
                rmax = fmaxf(rmax, __shfl_xor_sync(0xffffffffu, rmax, off));
            const float mn    = fmaxf(mrun[i], rmax);
            const float alpha = __expf(mrun[i] - mn);
            float rsum = 0.f;
            #pragma unroll
            for (int j = 0; j < 4; j++) {
                const float p = __expf(s[i][j] - mn);
                Ps_s[(ty*4+i)*64 + tx*4 + j] = p;
                rsum += p;
            }
            #pragma unroll
            for (int off = 8; off >= 1; off >>= 1)
                rsum += __shfl_xor_sync(0xffffffffu, rsum, off);
            lrun[i] = lrun[i]*alpha + rsum;
            mrun[i] = mn;
            #pragma unroll
            for (int j = 0; j < 4; j++) O[i][j] *= alpha;
        }
        __syncthreads();
        // GEMM2: O += Ptilde @ V, V[c][d] = Kt_s[d][c]
        #pragma unroll 8
        for (int c = 0; c < 64; c++) {
            float a[4], bb[4];
            #pragma unroll
            for (int i = 0; i < 4; i++) a[i]  = Ps_s[(ty*4+i)*64 + c];
            #pragma unroll
            for (int j = 0; j < 4; j++) bb[j] = Kt_s[(tx*4+j)*65 + c];
            #pragma unroll
            for (int i = 0; i < 4; i++)
                #pragma unroll
                for (int j = 0; j < 4; j++)
                    O[i][j] = fmaf(a[i], bb[j], O[i][j]);
        }
    }
    // Epilogue: normalize, write nudged in [b][w][c] layout
    #pragma unroll
    for (int i = 0; i < 4; i++) {
        const float inv = 1.0f / lrun[i];
        const int w = w0 + ty*4 + i;
        const float4 o4 = make_float4(O[i][0]*inv, O[i][1]*inv, O[i][2]*inv, O[i][3]*inv);
        *(float4*)&g_Ng[((size_t)(b*W_ + w))*C_ + n*K_ + tx*4] = o4;
    }
}

// ---------------------------------------------------------------------------
extern "C" void kernel_launch(void* const* d_in, const int* in_sizes, int n_in,
                              void* d_out, int out_size) {
    const float* x  = (const float*)d_in[0];  // [B,W,C]
    const float* Wp = (const float*)d_in[1];  // [C,C]
    const float* bp = (const float*)d_in[2];  // [C]
    const float* G  = (const float*)d_in[3];  // [1,N,W,K]
    const float* Wm = (const float*)d_in[4];  // [C,C]
    const float* bm = (const float*)d_in[5];  // [C]
    float* out = (float*)d_out;

    // >48KB dynamic smem opt-in (attribute API, not a stream op; idempotent)
    cudaFuncSetAttribute(flash_kernel, cudaFuncAttributeMaxDynamicSharedMemorySize,
                         (4096 + 4096 + 64*65) * (int)sizeof(float));

    dim3 blk(16, 16);
    gemm_kernel<0><<<dim3(16, 64), blk>>>(x, Wp, bp, nullptr);
    mbuild_kernel<<<32, blk>>>(G);
    flash_kernel<<<dim3(32, 32), blk, (4096 + 4096 + 64*65)*sizeof(float)>>>();
    gemm_kernel<1><<<dim3(16, 64), blk>>>(nullptr, Wm, bm, out);
}